// round 15
// baseline (speedup 1.0000x reference)
#include <cuda_runtime.h>
#include <cuda_fp16.h>
#include <math.h>
#include <stdint.h>

constexpr int NSEQ = 384;
constexpr int CIN  = 128;
constexpr int NH   = 4;
constexpr int CHD  = 32;
constexpr int NTOK = NSEQ * NSEQ;
constexpr float QSCALE = 0.17677669529663687f;  // 1/sqrt(32)
constexpr float LOG2E  = 1.4426950408889634f;

// ---- scratch ----
__device__ __half g_qh [NTOK * CIN];   // pre-scaled by QSCALE*LOG2E
__device__ __half g_kh [NTOK * CIN];
__device__ __half g_vh [NTOK * CIN];
__device__ __half g_gh [NTOK * CIN];
__device__ __half g_ogh[NTOK * CIN];
__device__ __half g_trih[NH * NTOK];   // [h][q*NSEQ+k], pre-scaled by LOG2E

__device__ __forceinline__ uint32_t h2u(__half2 h) { return *(uint32_t*)&h; }
__device__ __forceinline__ float fexp2(float x) {
    float r; asm("ex2.approx.f32 %0, %1;" : "=f"(r) : "f"(x)); return r;
}
__device__ __forceinline__ uint32_t hexp2x2(uint32_t x) {
    uint32_t r; asm("ex2.approx.f16x2 %0, %1;" : "=r"(r) : "r"(x)); return r;
}

__device__ __forceinline__ void ldm_x4(uint32_t* r, const void* p) {
    uint32_t a = (uint32_t)__cvta_generic_to_shared(p);
    asm volatile("ldmatrix.sync.aligned.m8n8.x4.shared.b16 {%0,%1,%2,%3}, [%4];"
        : "=r"(r[0]), "=r"(r[1]), "=r"(r[2]), "=r"(r[3]) : "r"(a));
}
__device__ __forceinline__ void ldm_x4t(uint32_t* r, const void* p) {
    uint32_t a = (uint32_t)__cvta_generic_to_shared(p);
    asm volatile("ldmatrix.sync.aligned.m8n8.x4.trans.shared.b16 {%0,%1,%2,%3}, [%4];"
        : "=r"(r[0]), "=r"(r[1]), "=r"(r[2]), "=r"(r[3]) : "r"(a));
}
// D += A(16x16) * B(16x8), fp16 in, fp32 accum
__device__ __forceinline__ void mma16(float* d, const uint32_t* a, const uint32_t* b) {
    asm volatile(
        "mma.sync.aligned.m16n8k16.row.col.f32.f16.f16.f32 "
        "{%0,%1,%2,%3},{%4,%5,%6,%7},{%8,%9},{%0,%1,%2,%3};"
        : "+f"(d[0]), "+f"(d[1]), "+f"(d[2]), "+f"(d[3])
        : "r"(a[0]), "r"(a[1]), "r"(a[2]), "r"(a[3]), "r"(b[0]), "r"(b[1]));
}

// ============================================================
// Kernel 1: fused LN + tri + 4-way projections (unchanged R14).
// ============================================================
constexpr int HS  = 136;  // halves per smem row (A/B tiles)
constexpr int WTS = 24;   // halves per w_tri smem row

__global__ __launch_bounds__(256, 2)
void proj_tc(const float* __restrict__ z,
             const float* __restrict__ ln_w,
             const float* __restrict__ ln_b,
             const float* __restrict__ w_tri,
             const float* __restrict__ wq, const float* __restrict__ wk,
             const float* __restrict__ wv, const float* __restrict__ wg) {
    extern __shared__ __half smh[];
    __half* As = smh;                         // 128 x HS
    __half* Bbuf[2] = { smh + 128 * HS, smh + 2 * 128 * HS };
    __half* Wt = smh + 3 * 128 * HS;          // 128 x WTS (w_tri padded)
    int tid = threadIdx.x, lane = tid & 31, warp = tid >> 5;
    int g = lane >> 2, t = lane & 3;
    int m0 = blockIdx.x * 128;
    const float* Ws[4] = { wq, wk, wv, wg };

    // ---- LN pass A: partial sums for 16 rows, batched shuffles ----
    float s1[16], s2[16];
    #pragma unroll
    for (int r = 0; r < 16; r++) {
        float4 x = *(const float4*)&z[(size_t)(m0 + warp * 16 + r) * CIN + lane * 4];
        s1[r] = x.x + x.y + x.z + x.w;
        s2[r] = x.x * x.x + x.y * x.y + x.z * x.z + x.w * x.w;
    }
    #pragma unroll
    for (int off = 16; off; off >>= 1)
        #pragma unroll
        for (int r = 0; r < 16; r++) {
            s1[r] += __shfl_xor_sync(~0u, s1[r], off);
            s2[r] += __shfl_xor_sync(~0u, s2[r], off);
        }

    // ---- LN pass B: normalize (z re-read hits L1), write As ----
    {
        float4 w4 = *(const float4*)&ln_w[lane * 4];
        float4 b4 = *(const float4*)&ln_b[lane * 4];
        #pragma unroll
        for (int r = 0; r < 16; r++) {
            int row = warp * 16 + r;
            float mean = s1[r] * (1.0f / CIN);
            float var  = s2[r] * (1.0f / CIN) - mean * mean;
            float rs   = rsqrtf(var + 1e-5f);
            float4 x = *(const float4*)&z[(size_t)(m0 + row) * CIN + lane * 4];
            float zn0 = (x.x - mean) * rs * w4.x + b4.x;
            float zn1 = (x.y - mean) * rs * w4.y + b4.y;
            float zn2 = (x.z - mean) * rs * w4.z + b4.z;
            float zn3 = (x.w - mean) * rs * w4.w + b4.w;
            uint2 u = { h2u(__floats2half2_rn(zn0, zn1)), h2u(__floats2half2_rn(zn2, zn3)) };
            *(uint2*)&As[row * HS + lane * 4] = u;
        }
    }

    // ---- w_tri tile (128 x 16 halves, cols 4..15 zero) ----
    if (tid < 128) {
        float4 v = *(const float4*)&w_tri[tid * NH];
        *(uint2*)&Wt[tid * WTS] = uint2{ h2u(__floats2half2_rn(v.x, v.y)),
                                         h2u(__floats2half2_rn(v.z, v.w)) };
        *(uint2*)&Wt[tid * WTS + 4]  = uint2{ 0u, 0u };
        *(uint2*)&Wt[tid * WTS + 8]  = uint2{ 0u, 0u };
        *(uint2*)&Wt[tid * WTS + 12] = uint2{ 0u, 0u };
    }

    // ---- B0: wq ----
    #pragma unroll
    for (int e = 0; e < 16; e++) {
        int f = tid + e * 256;
        int row = f >> 5, c4 = (f & 31) * 4;
        float4 v = *(const float4*)&wq[(size_t)row * CIN + c4];
        uint2 u = { h2u(__floats2half2_rn(v.x, v.y)), h2u(__floats2half2_rn(v.z, v.w)) };
        *(uint2*)&Bbuf[0][row * HS + c4] = u;
    }
    __syncthreads();

    // ---- tri via mma: warp handles rows warp*16..+15 ----
    {
        float ta[4] = {};
        #pragma unroll
        for (int kc2 = 0; kc2 < 4; kc2++) {
            uint32_t bf[4];
            ldm_x4t(bf, &Wt[(kc2 * 32 + lane) * WTS]);
            #pragma unroll
            for (int kk = 0; kk < 2; kk++) {
                uint32_t af[4];
                ldm_x4(af, &As[(warp * 16 + (lane & 15)) * HS
                               + (kc2 * 2 + kk) * 16 + (lane >> 4) * 8]);
                mma16(ta, af, &bf[kk * 2]);
            }
        }
        if (t < 2) {
            int r0 = m0 + warp * 16 + g;
            g_trih[(size_t)(2 * t)     * NTOK + r0]     = __float2half(ta[0] * LOG2E);
            g_trih[(size_t)(2 * t + 1) * NTOK + r0]     = __float2half(ta[1] * LOG2E);
            g_trih[(size_t)(2 * t)     * NTOK + r0 + 8] = __float2half(ta[2] * LOG2E);
            g_trih[(size_t)(2 * t + 1) * NTOK + r0 + 8] = __float2half(ta[3] * LOG2E);
        }
    }

    int wm = warp >> 1, wn = warp & 1;   // 4x2, warp tile 32m x 64n
    const float QS2 = QSCALE * LOG2E;

    for (int sel = 0; sel < 4; sel++) {
        __half* Bs = Bbuf[sel & 1];
        __half* Bn = Bbuf[(sel + 1) & 1];

        if (sel < 3) {
            const float* W = Ws[sel + 1];
            #pragma unroll
            for (int e = 0; e < 16; e++) {
                int f = tid + e * 256;
                int row = f >> 5, c4 = (f & 31) * 4;
                float4 v = *(const float4*)&W[(size_t)row * CIN + c4];
                uint2 u = { h2u(__floats2half2_rn(v.x, v.y)), h2u(__floats2half2_rn(v.z, v.w)) };
                *(uint2*)&Bn[row * HS + c4] = u;
            }
        }

        float acc[2][8][4] = {};
        #pragma unroll
        for (int kc2 = 0; kc2 < 4; kc2++) {
            uint32_t bf[8][4];
            #pragma unroll
            for (int nt = 0; nt < 8; nt++)
                ldm_x4t(bf[nt], &Bs[(kc2 * 32 + lane) * HS + wn * 64 + nt * 8]);
            #pragma unroll
            for (int kk = 0; kk < 2; kk++) {
                uint32_t af[2][4];
                #pragma unroll
                for (int mt = 0; mt < 2; mt++)
                    ldm_x4(af[mt], &As[(wm * 32 + mt * 16 + (lane & 15)) * HS
                                       + (kc2 * 2 + kk) * 16 + (lane >> 4) * 8]);
                #pragma unroll
                for (int nt = 0; nt < 8; nt++) {
                    mma16(acc[0][nt], af[0], &bf[nt][kk * 2]);
                    mma16(acc[1][nt], af[1], &bf[nt][kk * 2]);
                }
            }
        }

        #pragma unroll
        for (int mt = 0; mt < 2; mt++)
            #pragma unroll
            for (int nt = 0; nt < 8; nt++)
                #pragma unroll
                for (int hf = 0; hf < 2; hf++) {
                    int gm  = m0 + wm * 32 + mt * 16 + g + hf * 8;
                    int col = wn * 64 + nt * 8 + 2 * t;
                    float c0 = acc[mt][nt][hf * 2 + 0], c1 = acc[mt][nt][hf * 2 + 1];
                    size_t idx = (size_t)gm * CIN + col;
                    if (sel == 0)
                        *(uint32_t*)&g_qh[idx] = h2u(__floats2half2_rn(c0 * QS2, c1 * QS2));
                    else if (sel == 1)
                        *(uint32_t*)&g_kh[idx] = h2u(__floats2half2_rn(c0, c1));
                    else if (sel == 2)
                        *(uint32_t*)&g_vh[idx] = h2u(__floats2half2_rn(c0, c1));
                    else
                        *(uint32_t*)&g_gh[idx] = h2u(__floats2half2_rn(
                            1.0f / (1.0f + __expf(-c0)), 1.0f / (1.0f + __expf(-c1))));
                }
        __syncthreads();
    }
}

// ============================================================
// Kernel 2: attention. 3 CTAs/SM, 48-k chunks, f16x2 exp2.
// Row sums via fp32 FADD of the packed half P values (on the
// idle fma/alu pipes) — the ones-column mma is REMOVED.
// ============================================================
constexpr int KSS = 40;   // halves per K/V row

__global__ __launch_bounds__(256, 3)
void attn_tc(const float* __restrict__ mask) {
    int i = blockIdx.x, h = blockIdx.y;
    extern __shared__ __half smh[];
    __half* Ks  = smh;                  // 384 x 40
    __half* Vs  = smh + NSEQ * KSS;     // 384 x 40
    float*  bsm = (float*)(smh + 2 * NSEQ * KSS);  // 384

    int tid = threadIdx.x, lane = tid & 31, warp = tid >> 5;
    int g = lane >> 2, t = lane & 3;

    const __half* gK = g_kh + (size_t)(i * NSEQ) * CIN + h * CHD;
    const __half* gV = g_vh + (size_t)(i * NSEQ) * CIN + h * CHD;
    #pragma unroll
    for (int e = 0; e < 12; e++) {
        int f = tid + e * 256;              // 3072 4-half units
        int row = f >> 3, c4 = (f & 7) * 4;
        *(uint2*)&Ks[row * KSS + c4] = *(const uint2*)&gK[(size_t)row * CIN + c4];
        *(uint2*)&Vs[row * KSS + c4] = *(const uint2*)&gV[(size_t)row * CIN + c4];
    }
    {
        int k = tid;
        if (k < NSEQ) bsm[k] = LOG2E * 1e9f * (mask[i * NSEQ + k] - 1.0f);
        k += 256;
        if (k < NSEQ) bsm[k] = LOG2E * 1e9f * (mask[i * NSEQ + k] - 1.0f);
    }
    __syncthreads();

    const __half* trih = g_trih + (size_t)h * NTOK;

    for (int tile = warp; tile < 24; tile += 8) {
        int q0 = tile * 16;
        const __half* triA = trih + (size_t)(q0 + g) * NSEQ;
        const __half* triB = triA + (size_t)8 * NSEQ;

        const __half* gQ = g_qh + (size_t)(i * NSEQ + q0) * CIN + h * CHD;
        uint32_t qa_[2][4];
        #pragma unroll
        for (int kc = 0; kc < 2; kc++) {
            qa_[kc][0] = *(const uint32_t*)&gQ[(size_t)g * CIN + kc * 16 + 2 * t];
            qa_[kc][1] = *(const uint32_t*)&gQ[(size_t)(g + 8) * CIN + kc * 16 + 2 * t];
            qa_[kc][2] = *(const uint32_t*)&gQ[(size_t)g * CIN + kc * 16 + 2 * t + 8];
            qa_[kc][3] = *(const uint32_t*)&gQ[(size_t)(g + 8) * CIN + kc * 16 + 2 * t + 8];
        }

        float M0 = -1e30f, M1 = -1e30f, l0 = 0.f, l1 = 0.f;
        float O[4][4] = {};

        #pragma unroll
        for (int ch = 0; ch < 8; ch++) {      // 48-k chunks
            int k0c = ch * 48;

            // ---- QK scores (log2 domain) ----
            float s[6][4];
            #pragma unroll
            for (int nt = 0; nt < 6; nt++) {
                s[nt][0] = s[nt][1] = s[nt][2] = s[nt][3] = 0.f;
                uint32_t bf[4];
                ldm_x4(bf, &Ks[(k0c + nt * 8 + (lane & 7)) * KSS + (lane >> 3) * 8]);
                mma16(s[nt], qa_[0], &bf[0]);
                mma16(s[nt], qa_[1], &bf[2]);
            }

            // ---- biases (tri direct from L2) + chunk max ----
            float cm0 = -1e30f, cm1 = -1e30f;
            #pragma unroll
            for (int nt = 0; nt < 6; nt++) {
                int k = k0c + nt * 8 + 2 * t;
                float2 bb = *(const float2*)&bsm[k];
                float2 t0 = __half22float2(*(const __half2*)&triA[k]);
                float2 t1 = __half22float2(*(const __half2*)&triB[k]);
                s[nt][0] += bb.x + t0.x; s[nt][1] += bb.y + t0.y;
                s[nt][2] += bb.x + t1.x; s[nt][3] += bb.y + t1.y;
                cm0 = fmaxf(cm0, fmaxf(s[nt][0], s[nt][1]));
                cm1 = fmaxf(cm1, fmaxf(s[nt][2], s[nt][3]));
            }
            cm0 = fmaxf(cm0, __shfl_xor_sync(~0u, cm0, 1));
            cm0 = fmaxf(cm0, __shfl_xor_sync(~0u, cm0, 2));
            cm1 = fmaxf(cm1, __shfl_xor_sync(~0u, cm1, 1));
            cm1 = fmaxf(cm1, __shfl_xor_sync(~0u, cm1, 2));

            // ---- online rescale ----
            float Mn0 = fmaxf(M0, cm0), Mn1 = fmaxf(M1, cm1);
            float al0 = fexp2(M0 - Mn0), al1 = fexp2(M1 - Mn1);
            M0 = Mn0; M1 = Mn1;
            l0 *= al0; l1 *= al1;
            #pragma unroll
            for (int ct = 0; ct < 4; ct++) {
                O[ct][0] *= al0; O[ct][1] *= al0;
                O[ct][2] *= al1; O[ct][3] *= al1;
            }

            // ---- exp2 in f16x2 (output IS the P A-fragment) + fp32 sums ----
            uint32_t e[6][2];
            float cs0 = 0.f, cs1 = 0.f;
            #pragma unroll
            for (int nt = 0; nt < 6; nt++) {
                e[nt][0] = hexp2x2(h2u(__floats2half2_rn(s[nt][0] - M0, s[nt][1] - M0)));
                e[nt][1] = hexp2x2(h2u(__floats2half2_rn(s[nt][2] - M1, s[nt][3] - M1)));
                float2 p0 = __half22float2(*(const __half2*)&e[nt][0]);
                float2 p1 = __half22float2(*(const __half2*)&e[nt][1]);
                cs0 += p0.x + p0.y;
                cs1 += p1.x + p1.y;
            }
            cs0 += __shfl_xor_sync(~0u, cs0, 1); cs0 += __shfl_xor_sync(~0u, cs0, 2);
            cs1 += __shfl_xor_sync(~0u, cs1, 1); cs1 += __shfl_xor_sync(~0u, cs1, 2);
            l0 += cs0; l1 += cs1;

            // ---- AV (ones-column removed) ----
            #pragma unroll
            for (int j = 0; j < 3; j++) {       // k16 steps
                uint32_t pa[4] = { e[2 * j][0], e[2 * j][1],
                                   e[2 * j + 1][0], e[2 * j + 1][1] };
                #pragma unroll
                for (int ct2 = 0; ct2 < 2; ct2++) {
                    uint32_t vb[4];
                    ldm_x4t(vb, &Vs[(k0c + j * 16 + (lane & 15)) * KSS
                                    + ct2 * 16 + (lane >> 4) * 8]);
                    mma16(O[ct2 * 2 + 0], pa, &vb[0]);
                    mma16(O[ct2 * 2 + 1], pa, &vb[2]);
                }
            }
        }

        // ---- normalize, gate, store og ----
        float inv0 = 1.0f / l0, inv1 = 1.0f / l1;
        #pragma unroll
        for (int ct = 0; ct < 4; ct++) {
            int c = ct * 8 + 2 * t;
            size_t idx0 = (size_t)(i * NSEQ + q0 + g) * CIN + h * CHD + c;
            size_t idx1 = idx0 + (size_t)8 * CIN;
            float2 gg0 = __half22float2(*(const __half2*)&g_gh[idx0]);
            float2 gg1 = __half22float2(*(const __half2*)&g_gh[idx1]);
            *(uint32_t*)&g_ogh[idx0] = h2u(__floats2half2_rn(
                O[ct][0] * inv0 * gg0.x, O[ct][1] * inv0 * gg0.y));
            *(uint32_t*)&g_ogh[idx1] = h2u(__floats2half2_rn(
                O[ct][2] * inv1 * gg1.x, O[ct][3] * inv1 * gg1.y));
        }
    }
}

// ============================================================
// Kernel 3: out = og @ wo, fp16 mma (unchanged).
// ============================================================
__global__ __launch_bounds__(256, 2)
void out_tc(const float* __restrict__ wo, float* __restrict__ out) {
    extern __shared__ __half smh[];
    __half* As = smh;
    __half* Bs = smh + 128 * HS;
    int tid = threadIdx.x, lane = tid & 31, warp = tid >> 5;
    int g = lane >> 2, t = lane & 3;
    int m0 = blockIdx.x * 128;

    #pragma unroll
    for (int e = 0; e < 8; e++) {
        int f = tid + e * 256;
        int row = f >> 4, c8 = (f & 15) * 8;
        *(uint4*)&As[row * HS + c8] = *(const uint4*)&g_ogh[(size_t)(m0 + row) * CIN + c8];
    }
    #pragma unroll
    for (int e = 0; e < 16; e++) {
        int f = tid + e * 256;
        int row = f >> 5, c4 = (f & 31) * 4;
        float4 vb = *(const float4*)&wo[(size_t)row * CIN + c4];
        uint2 ub = { h2u(__floats2half2_rn(vb.x, vb.y)), h2u(__floats2half2_rn(vb.z, vb.w)) };
        *(uint2*)&Bs[row * HS + c4] = ub;
    }
    __syncthreads();

    int wm = warp >> 1, wn = warp & 1;
    float acc[2][8][4] = {};
    #pragma unroll
    for (int kc2 = 0; kc2 < 4; kc2++) {
        uint32_t bf[8][4];
        #pragma unroll
        for (int nt = 0; nt < 8; nt++)
            ldm_x4t(bf[nt], &Bs[(kc2 * 32 + lane) * HS + wn * 64 + nt * 8]);
        #pragma unroll
        for (int kk = 0; kk < 2; kk++) {
            uint32_t af[2][4];
            #pragma unroll
            for (int mt = 0; mt < 2; mt++)
                ldm_x4(af[mt], &As[(wm * 32 + mt * 16 + (lane & 15)) * HS
                                   + (kc2 * 2 + kk) * 16 + (lane >> 4) * 8]);
            #pragma unroll
            for (int nt = 0; nt < 8; nt++) {
                mma16(acc[0][nt], af[0], &bf[nt][kk * 2]);
                mma16(acc[1][nt], af[1], &bf[nt][kk * 2]);
            }
        }
    }
    #pragma unroll
    for (int mt = 0; mt < 2; mt++)
        #pragma unroll
        for (int nt = 0; nt < 8; nt++)
            #pragma unroll
            for (int hf = 0; hf < 2; hf++) {
                int gm  = m0 + wm * 32 + mt * 16 + g + hf * 8;
                int col = wn * 64 + nt * 8 + 2 * t;
                float2 o = { acc[mt][nt][hf * 2 + 0], acc[mt][nt][hf * 2 + 1] };
                *(float2*)&out[(size_t)gm * CIN + col] = o;
            }
}

// ============================================================
extern "C" void kernel_launch(void* const* d_in, const int* in_sizes, int n_in,
                              void* d_out, int out_size) {
    const float* z     = (const float*)d_in[0];
    const float* mask  = (const float*)d_in[1];
    const float* ln_w  = (const float*)d_in[2];
    const float* ln_b  = (const float*)d_in[3];
    const float* w_tri = (const float*)d_in[4];
    const float* wq    = (const float*)d_in[5];
    const float* wk    = (const float*)d_in[6];
    const float* wv    = (const float*)d_in[7];
    const float* wg    = (const float*)d_in[8];
    const float* wo    = (const float*)d_in[9];
    float* out = (float*)d_out;

    size_t proj_smem = (size_t)(3 * 128 * HS + 128 * WTS) * sizeof(__half);  // 110592
    cudaFuncSetAttribute(proj_tc, cudaFuncAttributeMaxDynamicSharedMemorySize, (int)proj_smem);
    proj_tc<<<NTOK / 128, 256, proj_smem>>>(z, ln_w, ln_b, w_tri, wq, wk, wv, wg);

    size_t att_smem = (size_t)(2 * NSEQ * KSS) * sizeof(__half) + NSEQ * sizeof(float); // 62976
    cudaFuncSetAttribute(attn_tc, cudaFuncAttributeMaxDynamicSharedMemorySize, (int)att_smem);
    dim3 ga(NSEQ, NH);
    attn_tc<<<ga, 256, att_smem>>>(mask);

    size_t out_smem = (size_t)(2 * 128 * HS) * sizeof(__half);   // 69632
    cudaFuncSetAttribute(out_tc, cudaFuncAttributeMaxDynamicSharedMemorySize, (int)out_smem);
    out_tc<<<NTOK / 128, 256, out_smem>>>(wo, out);
}

// round 16
// speedup vs baseline: 1.0877x; 1.0877x over previous
#include <cuda_runtime.h>
#include <cuda_fp16.h>
#include <math.h>
#include <stdint.h>

constexpr int NSEQ = 384;
constexpr int CIN  = 128;
constexpr int NH   = 4;
constexpr int CHD  = 32;
constexpr int NTOK = NSEQ * NSEQ;
constexpr float QSCALE = 0.17677669529663687f;  // 1/sqrt(32)
constexpr float LOG2E  = 1.4426950408889634f;

// ---- scratch ----
__device__ __half g_qh [NTOK * CIN];   // pre-scaled by QSCALE*LOG2E
__device__ __half g_kh [NTOK * CIN];
__device__ __half g_vh [NTOK * CIN];
__device__ __half g_gh [NTOK * CIN];
__device__ __half g_ogh[NTOK * CIN];
__device__ __half g_trih[NH * NTOK];   // [h][q*NSEQ+k], pre-scaled by LOG2E
__device__ __half g_wh [5 * CIN * CIN]; // wq,wk,wv,wg,wo as half
__device__ __half g_wth[CIN * NH];      // w_tri as half

__device__ __forceinline__ uint32_t h2u(__half2 h) { return *(uint32_t*)&h; }
__device__ __forceinline__ float fexp2(float x) {
    float r; asm("ex2.approx.f32 %0, %1;" : "=f"(r) : "f"(x)); return r;
}
__device__ __forceinline__ uint32_t hexp2x2(uint32_t x) {
    uint32_t r; asm("ex2.approx.f16x2 %0, %1;" : "=r"(r) : "r"(x)); return r;
}

__device__ __forceinline__ void ldm_x4(uint32_t* r, const void* p) {
    uint32_t a = (uint32_t)__cvta_generic_to_shared(p);
    asm volatile("ldmatrix.sync.aligned.m8n8.x4.shared.b16 {%0,%1,%2,%3}, [%4];"
        : "=r"(r[0]), "=r"(r[1]), "=r"(r[2]), "=r"(r[3]) : "r"(a));
}
__device__ __forceinline__ void ldm_x4t(uint32_t* r, const void* p) {
    uint32_t a = (uint32_t)__cvta_generic_to_shared(p);
    asm volatile("ldmatrix.sync.aligned.m8n8.x4.trans.shared.b16 {%0,%1,%2,%3}, [%4];"
        : "=r"(r[0]), "=r"(r[1]), "=r"(r[2]), "=r"(r[3]) : "r"(a));
}
// D += A(16x16) * B(16x8), fp16 in, fp32 accum
__device__ __forceinline__ void mma16(float* d, const uint32_t* a, const uint32_t* b) {
    asm volatile(
        "mma.sync.aligned.m16n8k16.row.col.f32.f16.f16.f32 "
        "{%0,%1,%2,%3},{%4,%5,%6,%7},{%8,%9},{%0,%1,%2,%3};"
        : "+f"(d[0]), "+f"(d[1]), "+f"(d[2]), "+f"(d[3])
        : "r"(a[0]), "r"(a[1]), "r"(a[2]), "r"(a[3]), "r"(b[0]), "r"(b[1]));
}

// ============================================================
// Kernel 0: one-shot weight conversion to half.
// ============================================================
__global__ __launch_bounds__(256)
void prep_w(const float* __restrict__ wq, const float* __restrict__ wk,
            const float* __restrict__ wv, const float* __restrict__ wg,
            const float* __restrict__ wo, const float* __restrict__ w_tri) {
    int idx = blockIdx.x * 256 + threadIdx.x;     // each handles 4 floats
    if (idx < 5 * 4096) {
        const float* srcs[5] = { wq, wk, wv, wg, wo };
        int m = idx >> 12, o = (idx & 4095) * 4;
        float4 v = *(const float4*)&srcs[m][o];
        uint2 u = { h2u(__floats2half2_rn(v.x, v.y)), h2u(__floats2half2_rn(v.z, v.w)) };
        *(uint2*)&g_wh[m * 16384 + o] = u;
    } else if (idx < 5 * 4096 + 128) {
        int t = idx - 5 * 4096;
        float4 v = *(const float4*)&w_tri[t * 4];
        uint2 u = { h2u(__floats2half2_rn(v.x, v.y)), h2u(__floats2half2_rn(v.z, v.w)) };
        *(uint2*)&g_wth[t * 4] = u;
    }
}

// ============================================================
// Kernel 1: fused LN + tri + 4-way projections.
// B tiles copied directly from pre-converted half weights.
// ============================================================
constexpr int HS  = 136;  // halves per smem row (A/B tiles)
constexpr int WTS = 24;   // halves per w_tri smem row

__global__ __launch_bounds__(256, 2)
void proj_tc(const float* __restrict__ z,
             const float* __restrict__ ln_w,
             const float* __restrict__ ln_b) {
    extern __shared__ __half smh[];
    __half* As = smh;                         // 128 x HS
    __half* Bbuf[2] = { smh + 128 * HS, smh + 2 * 128 * HS };
    __half* Wt = smh + 3 * 128 * HS;          // 128 x WTS (w_tri padded)
    int tid = threadIdx.x, lane = tid & 31, warp = tid >> 5;
    int g = lane >> 2, t = lane & 3;
    int m0 = blockIdx.x * 128;

    // ---- LN pass A: partial sums for 16 rows, batched shuffles ----
    float s1[16], s2[16];
    #pragma unroll
    for (int r = 0; r < 16; r++) {
        float4 x = *(const float4*)&z[(size_t)(m0 + warp * 16 + r) * CIN + lane * 4];
        s1[r] = x.x + x.y + x.z + x.w;
        s2[r] = x.x * x.x + x.y * x.y + x.z * x.z + x.w * x.w;
    }
    #pragma unroll
    for (int off = 16; off; off >>= 1)
        #pragma unroll
        for (int r = 0; r < 16; r++) {
            s1[r] += __shfl_xor_sync(~0u, s1[r], off);
            s2[r] += __shfl_xor_sync(~0u, s2[r], off);
        }

    // ---- LN pass B: normalize (z re-read), write As ----
    {
        float4 w4 = *(const float4*)&ln_w[lane * 4];
        float4 b4 = *(const float4*)&ln_b[lane * 4];
        #pragma unroll
        for (int r = 0; r < 16; r++) {
            int row = warp * 16 + r;
            float mean = s1[r] * (1.0f / CIN);
            float var  = s2[r] * (1.0f / CIN) - mean * mean;
            float rs   = rsqrtf(var + 1e-5f);
            float4 x = *(const float4*)&z[(size_t)(m0 + row) * CIN + lane * 4];
            float zn0 = (x.x - mean) * rs * w4.x + b4.x;
            float zn1 = (x.y - mean) * rs * w4.y + b4.y;
            float zn2 = (x.z - mean) * rs * w4.z + b4.z;
            float zn3 = (x.w - mean) * rs * w4.w + b4.w;
            uint2 u = { h2u(__floats2half2_rn(zn0, zn1)), h2u(__floats2half2_rn(zn2, zn3)) };
            *(uint2*)&As[row * HS + lane * 4] = u;
        }
    }

    // ---- w_tri tile (128 x 16 halves, cols 4..15 zero) ----
    if (tid < 128) {
        uint2 v = *(const uint2*)&g_wth[tid * NH];
        *(uint2*)&Wt[tid * WTS] = v;
        *(uint2*)&Wt[tid * WTS + 4]  = uint2{ 0u, 0u };
        *(uint2*)&Wt[tid * WTS + 8]  = uint2{ 0u, 0u };
        *(uint2*)&Wt[tid * WTS + 12] = uint2{ 0u, 0u };
    }

    // ---- B0: wq (half copy) ----
    #pragma unroll
    for (int e = 0; e < 8; e++) {
        int f = tid + e * 256;
        int row = f >> 4, c8 = (f & 15) * 8;
        *(uint4*)&Bbuf[0][row * HS + c8] = *(const uint4*)&g_wh[row * CIN + c8];
    }
    __syncthreads();

    // ---- tri via mma: warp handles rows warp*16..+15 ----
    {
        float ta[4] = {};
        #pragma unroll
        for (int kc2 = 0; kc2 < 4; kc2++) {
            uint32_t bf[4];
            ldm_x4t(bf, &Wt[(kc2 * 32 + lane) * WTS]);
            #pragma unroll
            for (int kk = 0; kk < 2; kk++) {
                uint32_t af[4];
                ldm_x4(af, &As[(warp * 16 + (lane & 15)) * HS
                               + (kc2 * 2 + kk) * 16 + (lane >> 4) * 8]);
                mma16(ta, af, &bf[kk * 2]);
            }
        }
        if (t < 2) {
            int r0 = m0 + warp * 16 + g;
            g_trih[(size_t)(2 * t)     * NTOK + r0]     = __float2half(ta[0] * LOG2E);
            g_trih[(size_t)(2 * t + 1) * NTOK + r0]     = __float2half(ta[1] * LOG2E);
            g_trih[(size_t)(2 * t)     * NTOK + r0 + 8] = __float2half(ta[2] * LOG2E);
            g_trih[(size_t)(2 * t + 1) * NTOK + r0 + 8] = __float2half(ta[3] * LOG2E);
        }
    }

    int wm = warp >> 1, wn = warp & 1;   // 4x2, warp tile 32m x 64n
    const float QS2 = QSCALE * LOG2E;

    for (int sel = 0; sel < 4; sel++) {
        __half* Bs = Bbuf[sel & 1];
        __half* Bn = Bbuf[(sel + 1) & 1];

        if (sel < 3) {
            const __half* W = g_wh + (size_t)(sel + 1) * 16384;
            #pragma unroll
            for (int e = 0; e < 8; e++) {
                int f = tid + e * 256;
                int row = f >> 4, c8 = (f & 15) * 8;
                *(uint4*)&Bn[row * HS + c8] = *(const uint4*)&W[row * CIN + c8];
            }
        }

        float acc[2][8][4] = {};
        #pragma unroll
        for (int kc2 = 0; kc2 < 4; kc2++) {
            uint32_t bf[8][4];
            #pragma unroll
            for (int nt = 0; nt < 8; nt++)
                ldm_x4t(bf[nt], &Bs[(kc2 * 32 + lane) * HS + wn * 64 + nt * 8]);
            #pragma unroll
            for (int kk = 0; kk < 2; kk++) {
                uint32_t af[2][4];
                #pragma unroll
                for (int mt = 0; mt < 2; mt++)
                    ldm_x4(af[mt], &As[(wm * 32 + mt * 16 + (lane & 15)) * HS
                                       + (kc2 * 2 + kk) * 16 + (lane >> 4) * 8]);
                #pragma unroll
                for (int nt = 0; nt < 8; nt++) {
                    mma16(acc[0][nt], af[0], &bf[nt][kk * 2]);
                    mma16(acc[1][nt], af[1], &bf[nt][kk * 2]);
                }
            }
        }

        #pragma unroll
        for (int mt = 0; mt < 2; mt++)
            #pragma unroll
            for (int nt = 0; nt < 8; nt++)
                #pragma unroll
                for (int hf = 0; hf < 2; hf++) {
                    int gm  = m0 + wm * 32 + mt * 16 + g + hf * 8;
                    int col = wn * 64 + nt * 8 + 2 * t;
                    float c0 = acc[mt][nt][hf * 2 + 0], c1 = acc[mt][nt][hf * 2 + 1];
                    size_t idx = (size_t)gm * CIN + col;
                    if (sel == 0)
                        *(uint32_t*)&g_qh[idx] = h2u(__floats2half2_rn(c0 * QS2, c1 * QS2));
                    else if (sel == 1)
                        *(uint32_t*)&g_kh[idx] = h2u(__floats2half2_rn(c0, c1));
                    else if (sel == 2)
                        *(uint32_t*)&g_vh[idx] = h2u(__floats2half2_rn(c0, c1));
                    else
                        *(uint32_t*)&g_gh[idx] = h2u(__floats2half2_rn(
                            1.0f / (1.0f + __expf(-c0)), 1.0f / (1.0f + __expf(-c1))));
                }
        __syncthreads();
    }
}

// ============================================================
// Kernel 2: attention. 3 CTAs/SM, 48-k chunks, f16x2 exp2,
// ones-column row sums (best-measured R14 config).
// ============================================================
constexpr int KSS = 40;   // halves per K/V row

__global__ __launch_bounds__(256, 3)
void attn_tc(const float* __restrict__ mask) {
    int i = blockIdx.x, h = blockIdx.y;
    extern __shared__ __half smh[];
    __half* Ks  = smh;                  // 384 x 40
    __half* Vs  = smh + NSEQ * KSS;     // 384 x 40
    float*  bsm = (float*)(smh + 2 * NSEQ * KSS);  // 384

    int tid = threadIdx.x, lane = tid & 31, warp = tid >> 5;
    int g = lane >> 2, t = lane & 3;

    const __half* gK = g_kh + (size_t)(i * NSEQ) * CIN + h * CHD;
    const __half* gV = g_vh + (size_t)(i * NSEQ) * CIN + h * CHD;
    #pragma unroll
    for (int e = 0; e < 12; e++) {
        int f = tid + e * 256;              // 3072 4-half units
        int row = f >> 3, c4 = (f & 7) * 4;
        *(uint2*)&Ks[row * KSS + c4] = *(const uint2*)&gK[(size_t)row * CIN + c4];
        *(uint2*)&Vs[row * KSS + c4] = *(const uint2*)&gV[(size_t)row * CIN + c4];
    }
    {
        int k = tid;
        if (k < NSEQ) bsm[k] = LOG2E * 1e9f * (mask[i * NSEQ + k] - 1.0f);
        k += 256;
        if (k < NSEQ) bsm[k] = LOG2E * 1e9f * (mask[i * NSEQ + k] - 1.0f);
    }
    __syncthreads();

    const __half* trih = g_trih + (size_t)h * NTOK;
    const uint32_t onesb[2] = { 0x3C003C00u, 0x3C003C00u };   // fp16 1.0 x2

    for (int tile = warp; tile < 24; tile += 8) {
        int q0 = tile * 16;
        const __half* triA = trih + (size_t)(q0 + g) * NSEQ;
        const __half* triB = triA + (size_t)8 * NSEQ;

        const __half* gQ = g_qh + (size_t)(i * NSEQ + q0) * CIN + h * CHD;
        uint32_t qa_[2][4];
        #pragma unroll
        for (int kc = 0; kc < 2; kc++) {
            qa_[kc][0] = *(const uint32_t*)&gQ[(size_t)g * CIN + kc * 16 + 2 * t];
            qa_[kc][1] = *(const uint32_t*)&gQ[(size_t)(g + 8) * CIN + kc * 16 + 2 * t];
            qa_[kc][2] = *(const uint32_t*)&gQ[(size_t)g * CIN + kc * 16 + 2 * t + 8];
            qa_[kc][3] = *(const uint32_t*)&gQ[(size_t)(g + 8) * CIN + kc * 16 + 2 * t + 8];
        }

        float M0 = -1e30f, M1 = -1e30f;
        float O[5][4] = {};    // O[4] = row-sum column (P @ ones)

        #pragma unroll
        for (int ch = 0; ch < 8; ch++) {      // 48-k chunks
            int k0c = ch * 48;

            // ---- QK scores (log2 domain) ----
            float s[6][4];
            #pragma unroll
            for (int nt = 0; nt < 6; nt++) {
                s[nt][0] = s[nt][1] = s[nt][2] = s[nt][3] = 0.f;
                uint32_t bf[4];
                ldm_x4(bf, &Ks[(k0c + nt * 8 + (lane & 7)) * KSS + (lane >> 3) * 8]);
                mma16(s[nt], qa_[0], &bf[0]);
                mma16(s[nt], qa_[1], &bf[2]);
            }

            // ---- biases (tri direct from L2) + chunk max ----
            float cm0 = -1e30f, cm1 = -1e30f;
            #pragma unroll
            for (int nt = 0; nt < 6; nt++) {
                int k = k0c + nt * 8 + 2 * t;
                float2 bb = *(const float2*)&bsm[k];
                float2 t0 = __half22float2(*(const __half2*)&triA[k]);
                float2 t1 = __half22float2(*(const __half2*)&triB[k]);
                s[nt][0] += bb.x + t0.x; s[nt][1] += bb.y + t0.y;
                s[nt][2] += bb.x + t1.x; s[nt][3] += bb.y + t1.y;
                cm0 = fmaxf(cm0, fmaxf(s[nt][0], s[nt][1]));
                cm1 = fmaxf(cm1, fmaxf(s[nt][2], s[nt][3]));
            }
            cm0 = fmaxf(cm0, __shfl_xor_sync(~0u, cm0, 1));
            cm0 = fmaxf(cm0, __shfl_xor_sync(~0u, cm0, 2));
            cm1 = fmaxf(cm1, __shfl_xor_sync(~0u, cm1, 1));
            cm1 = fmaxf(cm1, __shfl_xor_sync(~0u, cm1, 2));

            // ---- online rescale (O[4] sum column rescales with O) ----
            float Mn0 = fmaxf(M0, cm0), Mn1 = fmaxf(M1, cm1);
            float al0 = fexp2(M0 - Mn0), al1 = fexp2(M1 - Mn1);
            M0 = Mn0; M1 = Mn1;
            #pragma unroll
            for (int ct = 0; ct < 5; ct++) {
                O[ct][0] *= al0; O[ct][1] *= al0;
                O[ct][2] *= al1; O[ct][3] *= al1;
            }

            // ---- exp2 in f16x2: output IS the P A-fragment ----
            uint32_t e[6][2];
            #pragma unroll
            for (int nt = 0; nt < 6; nt++) {
                e[nt][0] = hexp2x2(h2u(__floats2half2_rn(s[nt][0] - M0, s[nt][1] - M0)));
                e[nt][1] = hexp2x2(h2u(__floats2half2_rn(s[nt][2] - M1, s[nt][3] - M1)));
            }

            // ---- AV + ones-column sum ----
            #pragma unroll
            for (int j = 0; j < 3; j++) {       // k16 steps
                uint32_t pa[4] = { e[2 * j][0], e[2 * j][1],
                                   e[2 * j + 1][0], e[2 * j + 1][1] };
                #pragma unroll
                for (int ct2 = 0; ct2 < 2; ct2++) {
                    uint32_t vb[4];
                    ldm_x4t(vb, &Vs[(k0c + j * 16 + (lane & 15)) * KSS
                                    + ct2 * 16 + (lane >> 4) * 8]);
                    mma16(O[ct2 * 2 + 0], pa, &vb[0]);
                    mma16(O[ct2 * 2 + 1], pa, &vb[2]);
                }
                mma16(O[4], pa, onesb);         // row sums
            }
        }

        // ---- normalize (l = ones column), gate, store og ----
        float inv0 = 1.0f / O[4][0], inv1 = 1.0f / O[4][2];
        #pragma unroll
        for (int ct = 0; ct < 4; ct++) {
            int c = ct * 8 + 2 * t;
            size_t idx0 = (size_t)(i * NSEQ + q0 + g) * CIN + h * CHD + c;
            size_t idx1 = idx0 + (size_t)8 * CIN;
            float2 gg0 = __half22float2(*(const __half2*)&g_gh[idx0]);
            float2 gg1 = __half22float2(*(const __half2*)&g_gh[idx1]);
            *(uint32_t*)&g_ogh[idx0] = h2u(__floats2half2_rn(
                O[ct][0] * inv0 * gg0.x, O[ct][1] * inv0 * gg0.y));
            *(uint32_t*)&g_ogh[idx1] = h2u(__floats2half2_rn(
                O[ct][2] * inv1 * gg1.x, O[ct][3] * inv1 * gg1.y));
        }
    }
}

// ============================================================
// Kernel 3: out = og @ wo. B copied from pre-converted half wo.
// ============================================================
__global__ __launch_bounds__(256, 2)
void out_tc(float* __restrict__ out) {
    extern __shared__ __half smh[];
    __half* As = smh;
    __half* Bs = smh + 128 * HS;
    int tid = threadIdx.x, lane = tid & 31, warp = tid >> 5;
    int g = lane >> 2, t = lane & 3;
    int m0 = blockIdx.x * 128;
    const __half* W = g_wh + (size_t)4 * 16384;

    #pragma unroll
    for (int e = 0; e < 8; e++) {
        int f = tid + e * 256;
        int row = f >> 4, c8 = (f & 15) * 8;
        *(uint4*)&As[row * HS + c8] = *(const uint4*)&g_ogh[(size_t)(m0 + row) * CIN + c8];
        *(uint4*)&Bs[row * HS + c8] = *(const uint4*)&W[row * CIN + c8];
    }
    __syncthreads();

    int wm = warp >> 1, wn = warp & 1;
    float acc[2][8][4] = {};
    #pragma unroll
    for (int kc2 = 0; kc2 < 4; kc2++) {
        uint32_t bf[8][4];
        #pragma unroll
        for (int nt = 0; nt < 8; nt++)
            ldm_x4t(bf[nt], &Bs[(kc2 * 32 + lane) * HS + wn * 64 + nt * 8]);
        #pragma unroll
        for (int kk = 0; kk < 2; kk++) {
            uint32_t af[2][4];
            #pragma unroll
            for (int mt = 0; mt < 2; mt++)
                ldm_x4(af[mt], &As[(wm * 32 + mt * 16 + (lane & 15)) * HS
                                   + (kc2 * 2 + kk) * 16 + (lane >> 4) * 8]);
            #pragma unroll
            for (int nt = 0; nt < 8; nt++) {
                mma16(acc[0][nt], af[0], &bf[nt][kk * 2]);
                mma16(acc[1][nt], af[1], &bf[nt][kk * 2]);
            }
        }
    }
    #pragma unroll
    for (int mt = 0; mt < 2; mt++)
        #pragma unroll
        for (int nt = 0; nt < 8; nt++)
            #pragma unroll
            for (int hf = 0; hf < 2; hf++) {
                int gm  = m0 + wm * 32 + mt * 16 + g + hf * 8;
                int col = wn * 64 + nt * 8 + 2 * t;
                float2 o = { acc[mt][nt][hf * 2 + 0], acc[mt][nt][hf * 2 + 1] };
                *(float2*)&out[(size_t)gm * CIN + col] = o;
            }
}

// ============================================================
extern "C" void kernel_launch(void* const* d_in, const int* in_sizes, int n_in,
                              void* d_out, int out_size) {
    const float* z     = (const float*)d_in[0];
    const float* mask  = (const float*)d_in[1];
    const float* ln_w  = (const float*)d_in[2];
    const float* ln_b  = (const float*)d_in[3];
    const float* w_tri = (const float*)d_in[4];
    const float* wq    = (const float*)d_in[5];
    const float* wk    = (const float*)d_in[6];
    const float* wv    = (const float*)d_in[7];
    const float* wg    = (const float*)d_in[8];
    const float* wo    = (const float*)d_in[9];
    float* out = (float*)d_out;

    prep_w<<<81, 256>>>(wq, wk, wv, wg, wo, w_tri);

    size_t proj_smem = (size_t)(3 * 128 * HS + 128 * WTS) * sizeof(__half);  // 110592
    cudaFuncSetAttribute(proj_tc, cudaFuncAttributeMaxDynamicSharedMemorySize, (int)proj_smem);
    proj_tc<<<NTOK / 128, 256, proj_smem>>>(z, ln_w, ln_b);

    size_t att_smem = (size_t)(2 * NSEQ * KSS) * sizeof(__half) + NSEQ * sizeof(float); // 62976
    cudaFuncSetAttribute(attn_tc, cudaFuncAttributeMaxDynamicSharedMemorySize, (int)att_smem);
    dim3 ga(NSEQ, NH);
    attn_tc<<<ga, 256, att_smem>>>(mask);

    size_t out_smem = (size_t)(2 * 128 * HS) * sizeof(__half);   // 69632
    cudaFuncSetAttribute(out_tc, cudaFuncAttributeMaxDynamicSharedMemorySize, (int)out_smem);
    out_tc<<<NTOK / 128, 256, out_smem>>>(out);
}